// round 15
// baseline (speedup 1.0000x reference)
#include <cuda_runtime.h>
#include <cuda_fp16.h>
#include <math.h>
#include <stdint.h>

#define HIDDEN   2048
#define NHEADS   16
#define HDIM     128
#define BATCH    2
#define SEQ      2048
#define BH       (BATCH * NHEADS)
#define MROWS    (BATCH * SEQ)
#define INV_NORM 0.08838834764831845f   // 1/sqrt(128)

#define KB        32                     // K elems per chunk (64B rows)
#define STAGE_B   16384                  // A 8K | B 8K (fp16 single)
#define NSTAGE    3
#define EPI_STR   132
#define SMEM_DYN  67584                  // max(3*16384, 128*132*4)

#define CTX_RS    67584
#define CTX_SMEM  68096

// ===================== scratch (static __device__, no allocation) ============
__device__ __align__(128) __half g_p[(size_t)BH * SEQ * SEQ];           // 256MB
__device__ __align__(128) float g_psum[(size_t)BH * 16 * SEQ];          // 4MB

__device__ __align__(128) __half g_x[(size_t)MROWS * HIDDEN];
__device__ __align__(128) __half g_wq[(size_t)HIDDEN * HIDDEN];
__device__ __align__(128) __half g_wk[(size_t)HIDDEN * HIDDEN];
__device__ __align__(128) __half g_wv[(size_t)HIDDEN * HIDDEN];
__device__ __align__(128) __half g_wd[(size_t)HIDDEN * HIDDEN];

__device__ __align__(128) __half g_q[(size_t)BH * SEQ * HDIM];
__device__ __align__(128) __half g_k[(size_t)BH * SEQ * HDIM];
__device__ __align__(128) __half g_vT[(size_t)BH * HDIM * SEQ];
__device__ __align__(128) __half g_c[(size_t)MROWS * HIDDEN];

// ===================== helpers ===============================================
static __device__ __forceinline__ uint32_t s2u(const void* p) {
    uint32_t a;
    asm("{ .reg .u64 t; cvta.to.shared.u64 t, %1; cvt.u32.u64 %0, t; }"
        : "=r"(a) : "l"(p));
    return a;
}
static __device__ __forceinline__ void ldm4(uint32_t (&r)[4], uint32_t addr) {
    asm volatile("ldmatrix.sync.aligned.m8n8.x4.shared.b16 {%0,%1,%2,%3}, [%4];"
                 : "=r"(r[0]), "=r"(r[1]), "=r"(r[2]), "=r"(r[3]) : "r"(addr));
}
static __device__ __forceinline__ void mma16816h(float (&c)[4],
                                                 const uint32_t (&a)[4],
                                                 const uint32_t* b) {
    asm volatile("mma.sync.aligned.m16n8k16.row.col.f32.f16.f16.f32 "
                 "{%0,%1,%2,%3}, {%4,%5,%6,%7}, {%8,%9}, {%0,%1,%2,%3};"
                 : "+f"(c[0]), "+f"(c[1]), "+f"(c[2]), "+f"(c[3])
                 : "r"(a[0]), "r"(a[1]), "r"(a[2]), "r"(a[3]),
                   "r"(b[0]), "r"(b[1]));
}
static __device__ __forceinline__ void cpa16(uint32_t so, const void* g) {
    asm volatile("cp.async.cg.shared.global [%0], [%1], 16;" :: "r"(so), "l"(g));
}
static __device__ __forceinline__ uint32_t swz(int row, int c16) {       // 64B rows
    return (uint32_t)(row * 64 + ((c16 ^ ((row >> 1) & 3)) << 4));
}

// ===================== fp16 GEMM core: 128x128 tile, 128 thr, 64x64 warps ====
// 4 warps: wm = wid&1 (64 rows), wn = wid>>1 (64 cols). acc[4][8][4] = 128 regs.
static __device__ __forceinline__ void mma_gemm_h(
    const __half* __restrict__ A, const __half* __restrict__ B,
    int K, int lda, int ldb, float (&acc)[4][8][4]) {
    extern __shared__ char smem[];
    const uint32_t sb = s2u(smem);
    const int tid  = threadIdx.x;
    const int lane = tid & 31;
    const int wid  = tid >> 5;
    const int wm   = wid & 1;
    const int wn   = wid >> 1;
    const int NC   = K >> 5;             // 32-K chunks

    const int lrow = tid;                // 0..127, 4 x 16B per tile per thread

#define ISSUE(cc)                                                              \
    {                                                                          \
        const int _c = (cc);                                                   \
        const uint32_t sbase = sb + (_c % NSTAGE) * STAGE_B;                   \
        const char* ga = (const char*)(A + (size_t)lrow * lda + _c * KB);      \
        const char* gb = (const char*)(B + (size_t)lrow * ldb + _c * KB);      \
        _Pragma("unroll")                                                      \
        for (int u = 0; u < 4; u++) {                                          \
            const uint32_t so = swz(lrow, u);                                  \
            cpa16(sbase + so,        ga + u * 16);                             \
            cpa16(sbase + 8192 + so, gb + u * 16);                             \
        }                                                                      \
        asm volatile("cp.async.commit_group;" ::: "memory");                   \
    }

    ISSUE(0);
    if (NC > 1) ISSUE(1);

    const int arow_in = lane & 15;
    const int akh     = lane >> 4;
    const int brow_in = ((lane >> 4) << 3) + (lane & 7);
    const int bkh     = (lane >> 3) & 1;

    for (int c = 0; c < NC; c++) {
        if (c + 1 < NC) {
            asm volatile("cp.async.wait_group 1;" ::: "memory");
        } else {
            asm volatile("cp.async.wait_group 0;" ::: "memory");
        }
        __syncthreads();
        if (c + 2 < NC) ISSUE(c + 2);

        const uint32_t st = sb + (c % NSTAGE) * STAGE_B;
#pragma unroll
        for (int kk = 0; kk < 2; kk++) {
            uint32_t bF[4][4];
#pragma unroll
            for (int nj = 0; nj < 4; nj++) {
                const int row = wn * 64 + nj * 16 + brow_in;
                ldm4(bF[nj], st + 8192 + swz(row, kk * 2 + bkh));
            }
#pragma unroll
            for (int mi = 0; mi < 4; mi++) {
                const int row = wm * 64 + mi * 16 + arow_in;
                uint32_t aF[4];
                ldm4(aF, st + swz(row, kk * 2 + akh));
#pragma unroll
                for (int ni = 0; ni < 8; ni++)
                    mma16816h(acc[mi][ni], aF, &bF[ni >> 1][(ni & 1) * 2]);
            }
        }
    }
    __syncthreads();
#undef ISSUE
}

static __device__ __forceinline__ void acc_to_smem(float (&acc)[4][8][4]) {
    extern __shared__ char smem[];
    float* ep = (float*)smem;
    const int lane = threadIdx.x & 31;
    const int wid  = threadIdx.x >> 5;
    const int wm = wid & 1, wn = wid >> 1;
#pragma unroll
    for (int mi = 0; mi < 4; mi++)
#pragma unroll
        for (int ni = 0; ni < 8; ni++) {
            const int r0 = wm * 64 + mi * 16 + (lane >> 2);
            const int c0 = wn * 64 + ni * 8 + (lane & 3) * 2;
            ep[r0 * EPI_STR + c0]           = acc[mi][ni][0];
            ep[r0 * EPI_STR + c0 + 1]       = acc[mi][ni][1];
            ep[(r0 + 8) * EPI_STR + c0]     = acc[mi][ni][2];
            ep[(r0 + 8) * EPI_STR + c0 + 1] = acc[mi][ni][3];
        }
    __syncthreads();
}

// ===================== fp32 -> fp16 convert (one launch for all) =============
__global__ void __launch_bounds__(256)
cvt_all_kernel(const float* __restrict__ X,  const float* __restrict__ Wq,
               const float* __restrict__ Wk, const float* __restrict__ Wv,
               const float* __restrict__ Wd) {
    const int bid = blockIdx.x;
    const float* src;
    __half* dst;
    int rel;
    if (bid < 8192)       { src = X;  dst = g_x;  rel = bid; }
    else {
        const int w = (bid - 8192) >> 12;
        rel = (bid - 8192) & 4095;
        switch (w) {
            case 0:  src = Wq; dst = g_wq; break;
            case 1:  src = Wk; dst = g_wk; break;
            case 2:  src = Wv; dst = g_wv; break;
            default: src = Wd; dst = g_wd; break;
        }
    }
    const int i = rel * 256 + threadIdx.x;
    float4 v = ((const float4*)src)[i];
    __half2 hv[2] = { __halves2half2(__float2half(v.x), __float2half(v.y)),
                      __halves2half2(__float2half(v.z), __float2half(v.w)) };
    *(uint2*)(dst + (size_t)i * 4) = *(uint2*)hv;
}

// ===================== 1) QKV projection =====================================
__global__ void __launch_bounds__(128, 3)
qkv_kernel(const float* __restrict__ pbq, const float* __restrict__ pbk,
           const float* __restrict__ pbv) {
    const int mode = blockIdx.z;
    const int m0 = blockIdx.y * 128, n0 = blockIdx.x * 128;
    const __half* W = (mode == 0) ? g_wq : (mode == 1) ? g_wk : g_wv;
    const float* bias = (mode == 0) ? pbq : (mode == 1) ? pbk : pbv;

    float acc[4][8][4] = {};
    mma_gemm_h(g_x + (size_t)m0 * HIDDEN, W + (size_t)n0 * HIDDEN,
               HIDDEN, HIDDEN, HIDDEN, acc);
    acc_to_smem(acc);

    extern __shared__ char smem[];
    const float* ep = (const float*)smem;
    const int tid = threadIdx.x;
    const int half = tid & 1;
    const int h = blockIdx.x;

    if (mode == 2) {
        // vT: [bh][d][s]; thread owns one d-column, all 128 s values
        const int dcol = tid;
        const int b = m0 >> 11;
        const float bia = bias[n0 + dcol];
        const size_t base = ((size_t)(b * NHEADS + h) * HDIM + dcol) * SEQ +
                            (m0 & (SEQ - 1));
#pragma unroll 8
        for (int s = 0; s < 128; s += 2) {
            float v0 = ep[s * EPI_STR + dcol] + bia;
            float v1 = ep[(s + 1) * EPI_STR + dcol] + bia;
            *(__half2*)(g_vT + base + s) =
                __halves2half2(__float2half(v0), __float2half(v1));
        }
    } else {
        __half* dq = (mode == 0) ? g_q : g_k;
        const float* bi = bias + n0 + half * 64;
#pragma unroll
        for (int rr = 0; rr < 2; rr++) {
            const int r = rr * 64 + (tid >> 1);
            const int m = m0 + r;
            const int b = m >> 11, s = m & (SEQ - 1);
            const size_t base = ((size_t)(b * NHEADS + h) * SEQ + s) * HDIM +
                                half * 64;
            const float* er = ep + r * EPI_STR + half * 64;
#pragma unroll 8
            for (int cc = 0; cc < 64; cc += 2) {
                float v0 = er[cc] + bi[cc];
                float v1 = er[cc + 1] + bi[cc + 1];
                *(__half2*)(dq + base + cc) =
                    __halves2half2(__float2half(v0), __float2half(v1));
            }
        }
    }
}

// ===================== 2) scores -> P = exp(s) fp16 + partial row sums =======
__global__ void __launch_bounds__(128, 3)
scores_kernel(const float* __restrict__ alibi) {
    const int z = blockIdx.z;
    const int m0 = blockIdx.y * 128, n0 = blockIdx.x * 128;
    const size_t zo = (size_t)z * SEQ * HDIM;

    float acc[4][8][4] = {};
    mma_gemm_h(g_q + zo + (size_t)m0 * HDIM, g_k + zo + (size_t)n0 * HDIM,
               HDIM, HDIM, HDIM, acc);
    acc_to_smem(acc);

    extern __shared__ char smem[];
    const float* ep = (const float*)smem;
    const int tid = threadIdx.x;
    const int half = tid & 1;
    const float* al = alibi + (size_t)z * SEQ + n0 + half * 64;

#pragma unroll
    for (int rr = 0; rr < 2; rr++) {
        const int r = rr * 64 + (tid >> 1);
        const size_t prow = (size_t)z * SEQ * SEQ + (size_t)(m0 + r) * SEQ +
                            n0 + half * 64;
        const float* er = ep + r * EPI_STR + half * 64;
        float lsum = 0.f;
#pragma unroll 4
        for (int cc = 0; cc < 64; cc += 4) {
            float4 av = *(const float4*)(al + cc);
            float p0 = __expf(av.x + INV_NORM * er[cc + 0]);
            float p1 = __expf(av.y + INV_NORM * er[cc + 1]);
            float p2 = __expf(av.z + INV_NORM * er[cc + 2]);
            float p3 = __expf(av.w + INV_NORM * er[cc + 3]);
            lsum += (p0 + p1) + (p2 + p3);
            __half2 hv[2] = { __halves2half2(__float2half(p0), __float2half(p1)),
                              __halves2half2(__float2half(p2), __float2half(p3)) };
            *(uint2*)(g_p + prow + cc) = *(uint2*)hv;
        }
        lsum += __shfl_xor_sync(0xffffffffu, lsum, 1);
        if (half == 0)
            g_psum[((size_t)z * 16 + blockIdx.x) * SEQ + m0 + r] = lsum;
    }
}

// ===================== 3) ctx = P @ V, normalized ============================
__global__ void __launch_bounds__(128, 3)
ctx_kernel() {
    extern __shared__ char smem[];
    const int tid = threadIdx.x;
    const int z = blockIdx.z;
    const int m0 = blockIdx.y * 128;

    // reduce 16 partial sums per row into smem rowsum[128]
    {
        const float* ps = g_psum + (size_t)z * 16 * SEQ + m0 + tid;
        float s = 0.f;
#pragma unroll
        for (int nb = 0; nb < 16; nb++) s += ps[(size_t)nb * SEQ];
        ((float*)(smem + CTX_RS))[tid] = s;
    }

    const size_t po = (size_t)z * SEQ * SEQ + (size_t)m0 * SEQ;
    const size_t vo = (size_t)z * HDIM * SEQ;
    float acc[4][8][4] = {};
    mma_gemm_h(g_p + po, g_vT + vo, SEQ, SEQ, SEQ, acc);

    // normalize accumulators by 1/rowsum
    const int lane = tid & 31, wid = tid >> 5;
    const int wm = wid & 1;
    const float* rsm = (const float*)(smem + CTX_RS);
#pragma unroll
    for (int mi = 0; mi < 4; mi++) {
        const int r0 = wm * 64 + mi * 16 + (lane >> 2);
        const float inv0 = 1.0f / rsm[r0];
        const float inv1 = 1.0f / rsm[r0 + 8];
#pragma unroll
        for (int ni = 0; ni < 8; ni++) {
            acc[mi][ni][0] *= inv0;
            acc[mi][ni][1] *= inv0;
            acc[mi][ni][2] *= inv1;
            acc[mi][ni][3] *= inv1;
        }
    }
    acc_to_smem(acc);

    const float* ep = (const float*)smem;
    const int half = tid & 1;
    const int b = z / NHEADS, h = z % NHEADS;
#pragma unroll
    for (int rr = 0; rr < 2; rr++) {
        const int r = rr * 64 + (tid >> 1);
        const size_t base = ((size_t)(b * SEQ + m0 + r)) * HIDDEN +
                            h * HDIM + half * 64;
        const float* er = ep + r * EPI_STR + half * 64;
#pragma unroll 8
        for (int cc = 0; cc < 64; cc += 2) {
            *(__half2*)(g_c + base + cc) =
                __halves2half2(__float2half(er[cc]), __float2half(er[cc + 1]));
        }
    }
}

// ===================== 4) out = ctx @ Wd^T + bd + residual ===================
__global__ void __launch_bounds__(128, 3)
out_kernel(const float* __restrict__ bd, const float* __restrict__ residual,
           float* __restrict__ outp) {
    const int m0 = blockIdx.y * 128, n0 = blockIdx.x * 128;

    float acc[4][8][4] = {};
    mma_gemm_h(g_c + (size_t)m0 * HIDDEN, g_wd + (size_t)n0 * HIDDEN,
               HIDDEN, HIDDEN, HIDDEN, acc);
    acc_to_smem(acc);

    extern __shared__ char smem[];
    const float* ep = (const float*)smem;
    const int tid = threadIdx.x;
    const int half = tid & 1;
    const float* bi = bd + n0 + half * 64;
#pragma unroll
    for (int rr = 0; rr < 2; rr++) {
        const int r = rr * 64 + (tid >> 1);
        const size_t idx = (size_t)(m0 + r) * HIDDEN + n0 + half * 64;
        const float* er = ep + r * EPI_STR + half * 64;
        const float* rs = residual + idx;
        float* dst = outp + idx;
#pragma unroll 4
        for (int cc = 0; cc < 64; cc += 4) {
            float4 bv = *(const float4*)(bi + cc);
            float4 rv = *(const float4*)(rs + cc);
            float4 v;
            v.x = er[cc + 0] + bv.x + rv.x;
            v.y = er[cc + 1] + bv.y + rv.y;
            v.z = er[cc + 2] + bv.z + rv.z;
            v.w = er[cc + 3] + bv.w + rv.w;
            *(float4*)(dst + cc) = v;
        }
    }
}

// ===================== launch =================================================
extern "C" void kernel_launch(void* const* d_in, const int* in_sizes, int n_in,
                              void* d_out, int out_size) {
    const float* X        = (const float*)d_in[0];
    const float* residual = (const float*)d_in[1];
    const float* alibi    = (const float*)d_in[2];
    const float* Wq = (const float*)d_in[3];  const float* bq = (const float*)d_in[4];
    const float* Wk = (const float*)d_in[5];  const float* bk = (const float*)d_in[6];
    const float* Wv = (const float*)d_in[7];  const float* bv = (const float*)d_in[8];
    const float* Wd = (const float*)d_in[9];  const float* bd = (const float*)d_in[10];
    float* out = (float*)d_out;

    cudaFuncSetAttribute(qkv_kernel, cudaFuncAttributeMaxDynamicSharedMemorySize, SMEM_DYN);
    cudaFuncSetAttribute(scores_kernel, cudaFuncAttributeMaxDynamicSharedMemorySize, SMEM_DYN);
    cudaFuncSetAttribute(ctx_kernel, cudaFuncAttributeMaxDynamicSharedMemorySize, CTX_SMEM);
    cudaFuncSetAttribute(out_kernel, cudaFuncAttributeMaxDynamicSharedMemorySize, SMEM_DYN);

    cvt_all_kernel<<<8192 + 4 * 4096, 256>>>(X, Wq, Wk, Wv, Wd);

    qkv_kernel<<<dim3(16, 32, 3), 128, SMEM_DYN>>>(bq, bk, bv);
    scores_kernel<<<dim3(16, 16, 32), 128, SMEM_DYN>>>(alibi);
    ctx_kernel<<<dim3(1, 16, 32), 128, CTX_SMEM>>>();
    out_kernel<<<dim3(16, 32), 128, SMEM_DYN>>>(bd, residual, out);
}

// round 16
// speedup vs baseline: 1.3665x; 1.3665x over previous
#include <cuda_runtime.h>
#include <cuda_fp16.h>
#include <math.h>
#include <stdint.h>

#define HIDDEN   2048
#define NHEADS   16
#define HDIM     128
#define BATCH    2
#define SEQ      2048
#define BH       (BATCH * NHEADS)
#define MROWS    (BATCH * SEQ)
#define INV_NORM 0.08838834764831845f   // 1/sqrt(128)

#define KB        32                     // K elems per chunk (64B rows)
#define STAGE_B   16384                  // A 8K | B 8K  (fp16 single)
#define NSTAGE    3
#define EPI_STR   132
#define SMEM_DYN  67584                  // max(3*16384, 128*132*4)

#define CTX_RS    67584
#define CTX_SMEM  68096

// ===================== scratch (static __device__, no allocation) ============
__device__ __align__(128) __half g_p[(size_t)BH * SEQ * SEQ];           // 256MB
__device__ __align__(128) float g_psum[(size_t)BH * 16 * SEQ];          // 4MB

__device__ __align__(128) __half g_x[(size_t)MROWS * HIDDEN];
__device__ __align__(128) __half g_wq[(size_t)HIDDEN * HIDDEN];
__device__ __align__(128) __half g_wk[(size_t)HIDDEN * HIDDEN];
__device__ __align__(128) __half g_wv[(size_t)HIDDEN * HIDDEN];
__device__ __align__(128) __half g_wd[(size_t)HIDDEN * HIDDEN];

__device__ __align__(128) __half g_q[(size_t)BH * SEQ * HDIM];
__device__ __align__(128) __half g_k[(size_t)BH * SEQ * HDIM];
__device__ __align__(128) __half g_vT[(size_t)BH * HDIM * SEQ];
__device__ __align__(128) __half g_c[(size_t)MROWS * HIDDEN];

// ===================== helpers ===============================================
static __device__ __forceinline__ uint32_t s2u(const void* p) {
    uint32_t a;
    asm("{ .reg .u64 t; cvta.to.shared.u64 t, %1; cvt.u32.u64 %0, t; }"
        : "=r"(a) : "l"(p));
    return a;
}
static __device__ __forceinline__ void ldm4(uint32_t (&r)[4], uint32_t addr) {
    asm volatile("ldmatrix.sync.aligned.m8n8.x4.shared.b16 {%0,%1,%2,%3}, [%4];"
                 : "=r"(r[0]), "=r"(r[1]), "=r"(r[2]), "=r"(r[3]) : "r"(addr));
}
static __device__ __forceinline__ void mma16816h(float (&c)[4],
                                                 const uint32_t (&a)[4],
                                                 const uint32_t* b) {
    asm volatile("mma.sync.aligned.m16n8k16.row.col.f32.f16.f16.f32 "
                 "{%0,%1,%2,%3}, {%4,%5,%6,%7}, {%8,%9}, {%0,%1,%2,%3};"
                 : "+f"(c[0]), "+f"(c[1]), "+f"(c[2]), "+f"(c[3])
                 : "r"(a[0]), "r"(a[1]), "r"(a[2]), "r"(a[3]),
                   "r"(b[0]), "r"(b[1]));
}
static __device__ __forceinline__ void cpa16(uint32_t so, const void* g) {
    asm volatile("cp.async.cg.shared.global [%0], [%1], 16;" :: "r"(so), "l"(g));
}
static __device__ __forceinline__ uint32_t swz(int row, int c16) {       // 64B rows
    return (uint32_t)(row * 64 + ((c16 ^ ((row >> 1) & 3)) << 4));
}

// ===================== fp16 mma.sync GEMM core (128x128, 256 thr) ============
// C[128x128] = A[128xK] @ B[128xK]^T, fp16 single operands, fp32 acc. NT.
// 8 warps: wm = wid&1 (64 rows), wn = wid>>1 (32 cols). acc[4][4][4].
static __device__ __forceinline__ void mma_gemm_h(
    const __half* __restrict__ A, const __half* __restrict__ B,
    int K, int lda, int ldb, float (&acc)[4][4][4]) {
    extern __shared__ char smem[];
    const uint32_t sb = s2u(smem);
    const int tid  = threadIdx.x;
    const int lane = tid & 31;
    const int wid  = tid >> 5;
    const int wm   = wid & 1;
    const int wn   = wid >> 1;
    const int NC   = K >> 5;

    const int lrow = tid >> 1;           // 0..127
    const int lc0  = (tid & 1) * 2;      // 2 x 16B per thread per tile

#define ISSUE(cc)                                                              \
    {                                                                          \
        const int _c = (cc);                                                   \
        const uint32_t sbase = sb + (_c % NSTAGE) * STAGE_B;                   \
        const char* ga = (const char*)(A + (size_t)lrow * lda + _c * 32);      \
        const char* gb = (const char*)(B + (size_t)lrow * ldb + _c * 32);      \
        _Pragma("unroll")                                                      \
        for (int u = 0; u < 2; u++) {                                          \
            const int c16 = lc0 + u;                                           \
            const uint32_t so = swz(lrow, c16);                                \
            cpa16(sbase + so,        ga + c16 * 16);                           \
            cpa16(sbase + 8192 + so, gb + c16 * 16);                           \
        }                                                                      \
        asm volatile("cp.async.commit_group;" ::: "memory");                   \
    }

    ISSUE(0);
    if (NC > 1) ISSUE(1);

    const int arow_in = lane & 15;
    const int akh     = lane >> 4;
    const int brow_in = ((lane >> 4) << 3) + (lane & 7);
    const int bkh     = (lane >> 3) & 1;

    for (int c = 0; c < NC; c++) {
        if (c + 1 < NC) {
            asm volatile("cp.async.wait_group 1;" ::: "memory");
        } else {
            asm volatile("cp.async.wait_group 0;" ::: "memory");
        }
        __syncthreads();
        if (c + 2 < NC) ISSUE(c + 2);

        const uint32_t st = sb + (c % NSTAGE) * STAGE_B;
#pragma unroll
        for (int kk = 0; kk < 2; kk++) {
            // batch ALL fragment loads for this slab, then all MMAs
            uint32_t bF[2][4];
#pragma unroll
            for (int nj = 0; nj < 2; nj++) {
                const int row = wn * 32 + nj * 16 + brow_in;
                ldm4(bF[nj], st + 8192 + swz(row, kk * 2 + bkh));
            }
            uint32_t aF[4][4];
#pragma unroll
            for (int mi = 0; mi < 4; mi++) {
                const int row = wm * 64 + mi * 16 + arow_in;
                ldm4(aF[mi], st + swz(row, kk * 2 + akh));
            }
#pragma unroll
            for (int mi = 0; mi < 4; mi++)
#pragma unroll
                for (int ni = 0; ni < 4; ni++)
                    mma16816h(acc[mi][ni], aF[mi], &bF[ni >> 1][(ni & 1) * 2]);
        }
    }
    __syncthreads();
#undef ISSUE
}

static __device__ __forceinline__ void acc_to_smem(float (&acc)[4][4][4]) {
    extern __shared__ char smem[];
    float* ep = (float*)smem;
    const int lane = threadIdx.x & 31;
    const int wid  = threadIdx.x >> 5;
    const int wm = wid & 1, wn = wid >> 1;
#pragma unroll
    for (int mi = 0; mi < 4; mi++)
#pragma unroll
        for (int ni = 0; ni < 4; ni++) {
            const int r0 = wm * 64 + mi * 16 + (lane >> 2);
            const int c0 = wn * 32 + ni * 8 + (lane & 3) * 2;
            ep[r0 * EPI_STR + c0]           = acc[mi][ni][0];
            ep[r0 * EPI_STR + c0 + 1]       = acc[mi][ni][1];
            ep[(r0 + 8) * EPI_STR + c0]     = acc[mi][ni][2];
            ep[(r0 + 8) * EPI_STR + c0 + 1] = acc[mi][ni][3];
        }
    __syncthreads();
}

// ===================== fp32 -> fp16 convert (one launch for all) =============
__global__ void __launch_bounds__(256)
cvt_all_kernel(const float* __restrict__ X,  const float* __restrict__ Wq,
               const float* __restrict__ Wk, const float* __restrict__ Wv,
               const float* __restrict__ Wd) {
    const int bid = blockIdx.x;
    const float* src;
    __half* dst;
    int rel;
    if (bid < 8192)       { src = X;  dst = g_x;  rel = bid; }
    else {
        const int w = (bid - 8192) >> 12;
        rel = (bid - 8192) & 4095;
        switch (w) {
            case 0:  src = Wq; dst = g_wq; break;
            case 1:  src = Wk; dst = g_wk; break;
            case 2:  src = Wv; dst = g_wv; break;
            default: src = Wd; dst = g_wd; break;
        }
    }
    const int i = rel * 256 + threadIdx.x;
    float4 v = ((const float4*)src)[i];
    __half2 hv[2] = { __halves2half2(__float2half(v.x), __float2half(v.y)),
                      __halves2half2(__float2half(v.z), __float2half(v.w)) };
    *(uint2*)(dst + (size_t)i * 4) = *(uint2*)hv;
}

// ===================== 1) QKV projection =====================================
__global__ void __launch_bounds__(256, 2)
qkv_kernel(const float* __restrict__ pbq, const float* __restrict__ pbk,
           const float* __restrict__ pbv) {
    const int mode = blockIdx.z;
    const int m0 = blockIdx.y * 128, n0 = blockIdx.x * 128;
    const __half* W = (mode == 0) ? g_wq : (mode == 1) ? g_wk : g_wv;
    const float* bias = (mode == 0) ? pbq : (mode == 1) ? pbk : pbv;

    float acc[4][4][4] = {};
    mma_gemm_h(g_x + (size_t)m0 * HIDDEN, W + (size_t)n0 * HIDDEN,
               HIDDEN, HIDDEN, HIDDEN, acc);
    acc_to_smem(acc);

    extern __shared__ char smem[];
    const float* ep = (const float*)smem;
    const int tid = threadIdx.x;
    const int half = tid & 1;
    const int h = blockIdx.x;

    if (mode == 2) {
        // vT: [bh][d][s]
        const int dcol = tid >> 1;
        const int b = m0 >> 11;
        const float bia = bias[n0 + dcol];
        const size_t base = ((size_t)(b * NHEADS + h) * HDIM + dcol) * SEQ +
                            (m0 & (SEQ - 1)) + half * 64;
#pragma unroll 8
        for (int s = 0; s < 64; s += 2) {
            float v0 = ep[(half * 64 + s) * EPI_STR + dcol] + bia;
            float v1 = ep[(half * 64 + s + 1) * EPI_STR + dcol] + bia;
            *(__half2*)(g_vT + base + s) =
                __halves2half2(__float2half(v0), __float2half(v1));
        }
    } else {
        const int r = tid >> 1;
        const int m = m0 + r;
        const int b = m >> 11, s = m & (SEQ - 1);
        __half* dq = (mode == 0) ? g_q : g_k;
        const size_t base = ((size_t)(b * NHEADS + h) * SEQ + s) * HDIM + half * 64;
        const float* er = ep + r * EPI_STR + half * 64;
        const float* bi = bias + n0 + half * 64;
#pragma unroll 8
        for (int cc = 0; cc < 64; cc += 2) {
            float v0 = er[cc] + bi[cc];
            float v1 = er[cc + 1] + bi[cc + 1];
            *(__half2*)(dq + base + cc) =
                __halves2half2(__float2half(v0), __float2half(v1));
        }
    }
}

// ===================== 2) scores -> P = exp(s) fp16 + partial row sums =======
__global__ void __launch_bounds__(256, 2)
scores_kernel(const float* __restrict__ alibi) {
    const int z = blockIdx.z;
    const int m0 = blockIdx.y * 128, n0 = blockIdx.x * 128;
    const size_t zo = (size_t)z * SEQ * HDIM;

    float acc[4][4][4] = {};
    mma_gemm_h(g_q + zo + (size_t)m0 * HDIM, g_k + zo + (size_t)n0 * HDIM,
               HDIM, HDIM, HDIM, acc);
    acc_to_smem(acc);

    extern __shared__ char smem[];
    const float* ep = (const float*)smem;
    const int tid = threadIdx.x;
    const int r = tid >> 1, half = tid & 1;
    const float* al = alibi + (size_t)z * SEQ + n0 + half * 64;
    const size_t prow = (size_t)z * SEQ * SEQ + (size_t)(m0 + r) * SEQ +
                        n0 + half * 64;
    const float* er = ep + r * EPI_STR + half * 64;

    float lsum = 0.f;
#pragma unroll 4
    for (int cc = 0; cc < 64; cc += 4) {
        float4 av = *(const float4*)(al + cc);
        float p0 = __expf(av.x + INV_NORM * er[cc + 0]);
        float p1 = __expf(av.y + INV_NORM * er[cc + 1]);
        float p2 = __expf(av.z + INV_NORM * er[cc + 2]);
        float p3 = __expf(av.w + INV_NORM * er[cc + 3]);
        lsum += (p0 + p1) + (p2 + p3);
        __half2 hv[2] = { __halves2half2(__float2half(p0), __float2half(p1)),
                          __halves2half2(__float2half(p2), __float2half(p3)) };
        *(uint2*)(g_p + prow + cc) = *(uint2*)hv;
    }
    lsum += __shfl_xor_sync(0xffffffffu, lsum, 1);
    if (half == 0)
        g_psum[((size_t)z * 16 + blockIdx.x) * SEQ + m0 + r] = lsum;
}

// ===================== 3) ctx = P @ V, normalized ============================
__global__ void __launch_bounds__(256, 2)
ctx_kernel() {
    extern __shared__ char smem[];
    const int tid = threadIdx.x;
    const int z = blockIdx.z;
    const int m0 = blockIdx.y * 128;

    // reduce 16 partial sums per row into smem rowsum[128]
    {
        const int row = tid >> 1, half = tid & 1;
        const float* ps = g_psum + (size_t)z * 16 * SEQ + m0 + row;
        float s = 0.f;
#pragma unroll
        for (int nb = 0; nb < 8; nb++) s += ps[(size_t)(half * 8 + nb) * SEQ];
        s += __shfl_xor_sync(0xffffffffu, s, 1);
        ((float*)(smem + CTX_RS))[row] = s;
    }

    const size_t po = (size_t)z * SEQ * SEQ + (size_t)m0 * SEQ;
    const size_t vo = (size_t)z * HDIM * SEQ;
    float acc[4][4][4] = {};
    mma_gemm_h(g_p + po, g_vT + vo, SEQ, SEQ, SEQ, acc);

    // normalize accumulators by 1/rowsum
    const int lane = tid & 31, wid = tid >> 5;
    const int wm = wid & 1;
    const float* rsm = (const float*)(smem + CTX_RS);
#pragma unroll
    for (int mi = 0; mi < 4; mi++) {
        const int r0 = wm * 64 + mi * 16 + (lane >> 2);
        const float inv0 = 1.0f / rsm[r0];
        const float inv1 = 1.0f / rsm[r0 + 8];
#pragma unroll
        for (int ni = 0; ni < 4; ni++) {
            acc[mi][ni][0] *= inv0;
            acc[mi][ni][1] *= inv0;
            acc[mi][ni][2] *= inv1;
            acc[mi][ni][3] *= inv1;
        }
    }
    acc_to_smem(acc);

    const float* ep = (const float*)smem;
    const int r = tid >> 1, half = tid & 1;
    const int b = z / NHEADS, h = z % NHEADS;
    const size_t base = ((size_t)(b * SEQ + m0 + r)) * HIDDEN +
                        h * HDIM + half * 64;
    const float* er = ep + r * EPI_STR + half * 64;
#pragma unroll 8
    for (int cc = 0; cc < 64; cc += 2) {
        *(__half2*)(g_c + base + cc) =
            __halves2half2(__float2half(er[cc]), __float2half(er[cc + 1]));
    }
}

// ===================== 4) out = ctx @ Wd^T + bd + residual ===================
__global__ void __launch_bounds__(256, 2)
out_kernel(const float* __restrict__ bd, const float* __restrict__ residual,
           float* __restrict__ outp) {
    const int m0 = blockIdx.y * 128, n0 = blockIdx.x * 128;

    float acc[4][4][4] = {};
    mma_gemm_h(g_c + (size_t)m0 * HIDDEN, g_wd + (size_t)n0 * HIDDEN,
               HIDDEN, HIDDEN, HIDDEN, acc);
    acc_to_smem(acc);

    extern __shared__ char smem[];
    const float* ep = (const float*)smem;
    const int tid = threadIdx.x;
    const int r = tid >> 1, half = tid & 1;
    const size_t idx = (size_t)(m0 + r) * HIDDEN + n0 + half * 64;
    const float* er = ep + r * EPI_STR + half * 64;
    const float* bi = bd + n0 + half * 64;
    const float* rs = residual + idx;
    float* dst = outp + idx;
#pragma unroll 4
    for (int cc = 0; cc < 64; cc += 4) {
        float4 bv = *(const float4*)(bi + cc);
        float4 rv = *(const float4*)(rs + cc);
        float4 v;
        v.x = er[cc + 0] + bv.x + rv.x;
        v.y = er[cc + 1] + bv.y + rv.y;
        v.z = er[cc + 2] + bv.z + rv.z;
        v.w = er[cc + 3] + bv.w + rv.w;
        *(float4*)(dst + cc) = v;
    }
}

// ===================== launch =================================================
extern "C" void kernel_launch(void* const* d_in, const int* in_sizes, int n_in,
                              void* d_out, int out_size) {
    const float* X        = (const float*)d_in[0];
    const float* residual = (const float*)d_in[1];
    const float* alibi    = (const float*)d_in[2];
    const float* Wq = (const float*)d_in[3];  const float* bq = (const float*)d_in[4];
    const float* Wk = (const float*)d_in[5];  const float* bk = (const float*)d_in[6];
    const float* Wv = (const float*)d_in[7];  const float* bv = (const float*)d_in[8];
    const float* Wd = (const float*)d_in[9];  const float* bd = (const float*)d_in[10];
    float* out = (float*)d_out;

    cudaFuncSetAttribute(qkv_kernel, cudaFuncAttributeMaxDynamicSharedMemorySize, SMEM_DYN);
    cudaFuncSetAttribute(scores_kernel, cudaFuncAttributeMaxDynamicSharedMemorySize, SMEM_DYN);
    cudaFuncSetAttribute(ctx_kernel, cudaFuncAttributeMaxDynamicSharedMemorySize, CTX_SMEM);
    cudaFuncSetAttribute(out_kernel, cudaFuncAttributeMaxDynamicSharedMemorySize, SMEM_DYN);

    dim3 blk(256);
    cvt_all_kernel<<<8192 + 4 * 4096, blk>>>(X, Wq, Wk, Wv, Wd);

    qkv_kernel<<<dim3(16, 32, 3), blk, SMEM_DYN>>>(bq, bk, bv);
    scores_kernel<<<dim3(16, 16, 32), blk, SMEM_DYN>>>(alibi);
    ctx_kernel<<<dim3(1, 16, 32), blk, CTX_SMEM>>>();
    out_kernel<<<dim3(16, 32), blk, SMEM_DYN>>>(bd, residual, out);
}

// round 17
// speedup vs baseline: 1.3851x; 1.0136x over previous
#include <cuda_runtime.h>
#include <cuda_fp16.h>
#include <math.h>
#include <stdint.h>

#define HIDDEN   2048
#define NHEADS   16
#define HDIM     128
#define BATCH    2
#define SEQ      2048
#define BH       (BATCH * NHEADS)
#define MROWS    (BATCH * SEQ)
#define INV_NORM 0.08838834764831845f   // 1/sqrt(128)

#define KB2       64                     // K elems per chunk (128B rows)
#define STAGE_B   32768                  // A 16K | B 16K (fp16 single)
#define NSTAGE    3
#define EPI_STR   132
#define SMEM_DYN  (NSTAGE * STAGE_B)     // 98304 (covers 128*132*4 epilogue)

#define CTX_RS    98304
#define CTX_SMEM  98816

// ===================== scratch (static __device__, no allocation) ============
__device__ __align__(128) __half g_p[(size_t)BH * SEQ * SEQ];           // 256MB
__device__ __align__(128) float g_psum[(size_t)BH * 16 * SEQ];          // 4MB

__device__ __align__(128) __half g_x[(size_t)MROWS * HIDDEN];
__device__ __align__(128) __half g_wq[(size_t)HIDDEN * HIDDEN];
__device__ __align__(128) __half g_wk[(size_t)HIDDEN * HIDDEN];
__device__ __align__(128) __half g_wv[(size_t)HIDDEN * HIDDEN];
__device__ __align__(128) __half g_wd[(size_t)HIDDEN * HIDDEN];

__device__ __align__(128) __half g_q[(size_t)BH * SEQ * HDIM];
__device__ __align__(128) __half g_k[(size_t)BH * SEQ * HDIM];
__device__ __align__(128) __half g_vT[(size_t)BH * HDIM * SEQ];
__device__ __align__(128) __half g_c[(size_t)MROWS * HIDDEN];

// ===================== helpers ===============================================
static __device__ __forceinline__ uint32_t s2u(const void* p) {
    uint32_t a;
    asm("{ .reg .u64 t; cvta.to.shared.u64 t, %1; cvt.u32.u64 %0, t; }"
        : "=r"(a) : "l"(p));
    return a;
}
static __device__ __forceinline__ void ldm4(uint32_t (&r)[4], uint32_t addr) {
    asm volatile("ldmatrix.sync.aligned.m8n8.x4.shared.b16 {%0,%1,%2,%3}, [%4];"
                 : "=r"(r[0]), "=r"(r[1]), "=r"(r[2]), "=r"(r[3]) : "r"(addr));
}
static __device__ __forceinline__ void mma16816h(float (&c)[4],
                                                 const uint32_t (&a)[4],
                                                 const uint32_t* b) {
    asm volatile("mma.sync.aligned.m16n8k16.row.col.f32.f16.f16.f32 "
                 "{%0,%1,%2,%3}, {%4,%5,%6,%7}, {%8,%9}, {%0,%1,%2,%3};"
                 : "+f"(c[0]), "+f"(c[1]), "+f"(c[2]), "+f"(c[3])
                 : "r"(a[0]), "r"(a[1]), "r"(a[2]), "r"(a[3]),
                   "r"(b[0]), "r"(b[1]));
}
static __device__ __forceinline__ void cpa16(uint32_t so, const void* g) {
    asm volatile("cp.async.cg.shared.global [%0], [%1], 16;" :: "r"(so), "l"(g));
}
// swizzle for 128B rows (64 fp16): XOR c16 (0..7) with row&7 — conflict-free
static __device__ __forceinline__ uint32_t swz128(int row, int c16) {
    return (uint32_t)(row * 128 + ((c16 ^ (row & 7)) << 4));
}

// ===================== fp16 mma.sync GEMM core (128x128, 256 thr, K64) =======
// C[128x128] = A[128xK] @ B[128xK]^T. 8 warps: 64x32 warp tiles. acc[4][4][4].
// Cross-slab fragment double-buffering: slab kk+1's ldmatrix issues before
// slab kk's MMAs, hiding LDSM latency for 3 of 4 slabs per chunk.
static __device__ __forceinline__ void mma_gemm_h(
    const __half* __restrict__ A, const __half* __restrict__ B,
    int K, int lda, int ldb, float (&acc)[4][4][4]) {
    extern __shared__ char smem[];
    const uint32_t sb = s2u(smem);
    const int tid  = threadIdx.x;
    const int lane = tid & 31;
    const int wid  = tid >> 5;
    const int wm   = wid & 1;
    const int wn   = wid >> 1;
    const int NC   = K >> 6;             // 64-K chunks

    const int lrow = tid >> 1;           // 0..127
    const int lc0  = (tid & 1) * 4;      // 4 x 16B per thread per tile

#define ISSUE(cc)                                                              \
    {                                                                          \
        const int _c = (cc);                                                   \
        const uint32_t sbase = sb + (_c % NSTAGE) * STAGE_B;                   \
        const char* ga = (const char*)(A + (size_t)lrow * lda + _c * KB2);     \
        const char* gb = (const char*)(B + (size_t)lrow * ldb + _c * KB2);     \
        _Pragma("unroll")                                                      \
        for (int u = 0; u < 4; u++) {                                          \
            const int c16 = lc0 + u;                                           \
            const uint32_t so = swz128(lrow, c16);                             \
            cpa16(sbase + so,         ga + c16 * 16);                          \
            cpa16(sbase + 16384 + so, gb + c16 * 16);                          \
        }                                                                      \
        asm volatile("cp.async.commit_group;" ::: "memory");                   \
    }

    ISSUE(0);
    if (NC > 1) ISSUE(1);

    const int arow_in = lane & 15;
    const int akh     = lane >> 4;
    const int brow_in = ((lane >> 4) << 3) + (lane & 7);
    const int bkh     = (lane >> 3) & 1;

    uint32_t aF[2][4][4], bF[2][2][4];

#define LDFRAG(buf, kk_)                                                       \
    {                                                                          \
        const int _kk = (kk_);                                                 \
        _Pragma("unroll")                                                      \
        for (int nj = 0; nj < 2; nj++) {                                       \
            const int row = wn * 32 + nj * 16 + brow_in;                       \
            ldm4(bF[buf][nj], st + 16384 + swz128(row, _kk * 2 + bkh));        \
        }                                                                      \
        _Pragma("unroll")                                                      \
        for (int mi = 0; mi < 4; mi++) {                                       \
            const int row = wm * 64 + mi * 16 + arow_in;                       \
            ldm4(aF[buf][mi], st + swz128(row, _kk * 2 + akh));                \
        }                                                                      \
    }

    for (int c = 0; c < NC; c++) {
        if (c + 1 < NC) {
            asm volatile("cp.async.wait_group 1;" ::: "memory");
        } else {
            asm volatile("cp.async.wait_group 0;" ::: "memory");
        }
        __syncthreads();
        if (c + 2 < NC) ISSUE(c + 2);

        const uint32_t st = sb + (c % NSTAGE) * STAGE_B;
        LDFRAG(0, 0);
#pragma unroll
        for (int kk = 0; kk < 4; kk++) {
            const int cur = kk & 1;
            if (kk < 3) LDFRAG(1 - cur, kk + 1);
#pragma unroll
            for (int mi = 0; mi < 4; mi++)
#pragma unroll
                for (int ni = 0; ni < 4; ni++)
                    mma16816h(acc[mi][ni], aF[cur][mi],
                              &bF[cur][ni >> 1][(ni & 1) * 2]);
        }
    }
    __syncthreads();
#undef LDFRAG
#undef ISSUE
}

static __device__ __forceinline__ void acc_to_smem(float (&acc)[4][4][4]) {
    extern __shared__ char smem[];
    float* ep = (float*)smem;
    const int lane = threadIdx.x & 31;
    const int wid  = threadIdx.x >> 5;
    const int wm = wid & 1, wn = wid >> 1;
#pragma unroll
    for (int mi = 0; mi < 4; mi++)
#pragma unroll
        for (int ni = 0; ni < 4; ni++) {
            const int r0 = wm * 64 + mi * 16 + (lane >> 2);
            const int c0 = wn * 32 + ni * 8 + (lane & 3) * 2;
            ep[r0 * EPI_STR + c0]           = acc[mi][ni][0];
            ep[r0 * EPI_STR + c0 + 1]       = acc[mi][ni][1];
            ep[(r0 + 8) * EPI_STR + c0]     = acc[mi][ni][2];
            ep[(r0 + 8) * EPI_STR + c0 + 1] = acc[mi][ni][3];
        }
    __syncthreads();
}

// ===================== fp32 -> fp16 convert (one launch for all) =============
__global__ void __launch_bounds__(256)
cvt_all_kernel(const float* __restrict__ X,  const float* __restrict__ Wq,
               const float* __restrict__ Wk, const float* __restrict__ Wv,
               const float* __restrict__ Wd) {
    const int bid = blockIdx.x;
    const float* src;
    __half* dst;
    int rel;
    if (bid < 8192)       { src = X;  dst = g_x;  rel = bid; }
    else {
        const int w = (bid - 8192) >> 12;
        rel = (bid - 8192) & 4095;
        switch (w) {
            case 0:  src = Wq; dst = g_wq; break;
            case 1:  src = Wk; dst = g_wk; break;
            case 2:  src = Wv; dst = g_wv; break;
            default: src = Wd; dst = g_wd; break;
        }
    }
    const int i = rel * 256 + threadIdx.x;
    float4 v = ((const float4*)src)[i];
    __half2 hv[2] = { __halves2half2(__float2half(v.x), __float2half(v.y)),
                      __halves2half2(__float2half(v.z), __float2half(v.w)) };
    *(uint2*)(dst + (size_t)i * 4) = *(uint2*)hv;
}

// ===================== 1) QKV projection =====================================
__global__ void __launch_bounds__(256, 2)
qkv_kernel(const float* __restrict__ pbq, const float* __restrict__ pbk,
           const float* __restrict__ pbv) {
    const int mode = blockIdx.z;
    const int m0 = blockIdx.y * 128, n0 = blockIdx.x * 128;
    const __half* W = (mode == 0) ? g_wq : (mode == 1) ? g_wk : g_wv;
    const float* bias = (mode == 0) ? pbq : (mode == 1) ? pbk : pbv;

    float acc[4][4][4] = {};
    mma_gemm_h(g_x + (size_t)m0 * HIDDEN, W + (size_t)n0 * HIDDEN,
               HIDDEN, HIDDEN, HIDDEN, acc);
    acc_to_smem(acc);

    extern __shared__ char smem[];
    const float* ep = (const float*)smem;
    const int tid = threadIdx.x;
    const int half = tid & 1;
    const int h = blockIdx.x;

    if (mode == 2) {
        // vT: [bh][d][s]
        const int dcol = tid >> 1;
        const int b = m0 >> 11;
        const float bia = bias[n0 + dcol];
        const size_t base = ((size_t)(b * NHEADS + h) * HDIM + dcol) * SEQ +
                            (m0 & (SEQ - 1)) + half * 64;
#pragma unroll 8
        for (int s = 0; s < 64; s += 2) {
            float v0 = ep[(half * 64 + s) * EPI_STR + dcol] + bia;
            float v1 = ep[(half * 64 + s + 1) * EPI_STR + dcol] + bia;
            *(__half2*)(g_vT + base + s) =
                __halves2half2(__float2half(v0), __float2half(v1));
        }
    } else {
        const int r = tid >> 1;
        const int m = m0 + r;
        const int b = m >> 11, s = m & (SEQ - 1);
        __half* dq = (mode == 0) ? g_q : g_k;
        const size_t base = ((size_t)(b * NHEADS + h) * SEQ + s) * HDIM + half * 64;
        const float* er = ep + r * EPI_STR + half * 64;
        const float* bi = bias + n0 + half * 64;
#pragma unroll 8
        for (int cc = 0; cc < 64; cc += 2) {
            float v0 = er[cc] + bi[cc];
            float v1 = er[cc + 1] + bi[cc + 1];
            *(__half2*)(dq + base + cc) =
                __halves2half2(__float2half(v0), __float2half(v1));
        }
    }
}

// ===================== 2) scores -> P = exp(s) fp16 + partial row sums =======
__global__ void __launch_bounds__(256, 2)
scores_kernel(const float* __restrict__ alibi) {
    const int z = blockIdx.z;
    const int m0 = blockIdx.y * 128, n0 = blockIdx.x * 128;
    const size_t zo = (size_t)z * SEQ * HDIM;

    float acc[4][4][4] = {};
    mma_gemm_h(g_q + zo + (size_t)m0 * HDIM, g_k + zo + (size_t)n0 * HDIM,
               HDIM, HDIM, HDIM, acc);
    acc_to_smem(acc);

    extern __shared__ char smem[];
    const float* ep = (const float*)smem;
    const int tid = threadIdx.x;
    const int r = tid >> 1, half = tid & 1;
    const float* al = alibi + (size_t)z * SEQ + n0 + half * 64;
    const size_t prow = (size_t)z * SEQ * SEQ + (size_t)(m0 + r) * SEQ +
                        n0 + half * 64;
    const float* er = ep + r * EPI_STR + half * 64;

    float lsum = 0.f;
#pragma unroll 4
    for (int cc = 0; cc < 64; cc += 4) {
        float4 av = *(const float4*)(al + cc);
        float p0 = __expf(av.x + INV_NORM * er[cc + 0]);
        float p1 = __expf(av.y + INV_NORM * er[cc + 1]);
        float p2 = __expf(av.z + INV_NORM * er[cc + 2]);
        float p3 = __expf(av.w + INV_NORM * er[cc + 3]);
        lsum += (p0 + p1) + (p2 + p3);
        __half2 hv[2] = { __halves2half2(__float2half(p0), __float2half(p1)),
                          __halves2half2(__float2half(p2), __float2half(p3)) };
        *(uint2*)(g_p + prow + cc) = *(uint2*)hv;
    }
    lsum += __shfl_xor_sync(0xffffffffu, lsum, 1);
    if (half == 0)
        g_psum[((size_t)z * 16 + blockIdx.x) * SEQ + m0 + r] = lsum;
}

// ===================== 3) ctx = P @ V, normalized ============================
__global__ void __launch_bounds__(256, 2)
ctx_kernel() {
    extern __shared__ char smem[];
    const int tid = threadIdx.x;
    const int z = blockIdx.z;
    const int m0 = blockIdx.y * 128;

    // reduce 16 partial sums per row into smem rowsum[128]
    {
        const int row = tid >> 1, half = tid & 1;
        const float* ps = g_psum + (size_t)z * 16 * SEQ + m0 + row;
        float s = 0.f;
#pragma unroll
        for (int nb = 0; nb < 8; nb++) s += ps[(size_t)(half * 8 + nb) * SEQ];
        s += __shfl_xor_sync(0xffffffffu, s, 1);
        ((float*)(smem + CTX_RS))[row] = s;
    }

    const size_t po = (size_t)z * SEQ * SEQ + (size_t)m0 * SEQ;
    const size_t vo = (size_t)z * HDIM * SEQ;
    float acc[4][4][4] = {};
    mma_gemm_h(g_p + po, g_vT + vo, SEQ, SEQ, SEQ, acc);

    // normalize accumulators by 1/rowsum
    const int lane = tid & 31, wid = tid >> 5;
    const int wm = wid & 1;
    const float* rsm = (const float*)(smem + CTX_RS);
#pragma unroll
    for (int mi = 0; mi < 4; mi++) {
        const int r0 = wm * 64 + mi * 16 + (lane >> 2);
        const float inv0 = 1.0f / rsm[r0];
        const float inv1 = 1.0f / rsm[r0 + 8];
#pragma unroll
        for (int ni = 0; ni < 4; ni++) {
            acc[mi][ni][0] *= inv0;
            acc[mi][ni][1] *= inv0;
            acc[mi][ni][2] *= inv1;
            acc[mi][ni][3] *= inv1;
        }
    }
    acc_to_smem(acc);

    const float* ep = (const float*)smem;
    const int r = tid >> 1, half = tid & 1;
    const int b = z / NHEADS, h = z % NHEADS;
    const size_t base = ((size_t)(b * SEQ + m0 + r)) * HIDDEN +
                        h * HDIM + half * 64;
    const float* er = ep + r * EPI_STR + half * 64;
#pragma unroll 8
    for (int cc = 0; cc < 64; cc += 2) {
        *(__half2*)(g_c + base + cc) =
            __halves2half2(__float2half(er[cc]), __float2half(er[cc + 1]));
    }
}

// ===================== 4) out = ctx @ Wd^T + bd + residual ===================
__global__ void __launch_bounds__(256, 2)
out_kernel(const float* __restrict__ bd, const float* __restrict__ residual,
           float* __restrict__ outp) {
    const int m0 = blockIdx.y * 128, n0 = blockIdx.x * 128;

    float acc[4][4][4] = {};
    mma_gemm_h(g_c + (size_t)m0 * HIDDEN, g_wd + (size_t)n0 * HIDDEN,
               HIDDEN, HIDDEN, HIDDEN, acc);
    acc_to_smem(acc);

    extern __shared__ char smem[];
    const float* ep = (const float*)smem;
    const int tid = threadIdx.x;
    const int r = tid >> 1, half = tid & 1;
    const size_t idx = (size_t)(m0 + r) * HIDDEN + n0 + half * 64;
    const float* er = ep + r * EPI_STR + half * 64;
    const float* bi = bd + n0 + half * 64;
    const float* rs = residual + idx;
    float* dst = outp + idx;
#pragma unroll 4
    for (int cc = 0; cc < 64; cc += 4) {
        float4 bv = *(const float4*)(bi + cc);
        float4 rv = *(const float4*)(rs + cc);
        float4 v;
        v.x = er[cc + 0] + bv.x + rv.x;
        v.y = er[cc + 1] + bv.y + rv.y;
        v.z = er[cc + 2] + bv.z + rv.z;
        v.w = er[cc + 3] + bv.w + rv.w;
        *(float4*)(dst + cc) = v;
    }
}

// ===================== launch =================================================
extern "C" void kernel_launch(void* const* d_in, const int* in_sizes, int n_in,
                              void* d_out, int out_size) {
    const float* X        = (const float*)d_in[0];
    const float* residual = (const float*)d_in[1];
    const float* alibi    = (const float*)d_in[2];
    const float* Wq = (const float*)d_in[3];  const float* bq = (const float*)d_in[4];
    const float* Wk = (const float*)d_in[5];  const float* bk = (const float*)d_in[6];
    const float* Wv = (const float*)d_in[7];  const float* bv = (const float*)d_in[8];
    const float* Wd = (const float*)d_in[9];  const float* bd = (const float*)d_in[10];
    float* out = (float*)d_out;

    cudaFuncSetAttribute(qkv_kernel, cudaFuncAttributeMaxDynamicSharedMemorySize, SMEM_DYN);
    cudaFuncSetAttribute(scores_kernel, cudaFuncAttributeMaxDynamicSharedMemorySize, SMEM_DYN);
    cudaFuncSetAttribute(ctx_kernel, cudaFuncAttributeMaxDynamicSharedMemorySize, CTX_SMEM);
    cudaFuncSetAttribute(out_kernel, cudaFuncAttributeMaxDynamicSharedMemorySize, SMEM_DYN);

    dim3 blk(256);
    cvt_all_kernel<<<8192 + 4 * 4096, blk>>>(X, Wq, Wk, Wv, Wd);

    qkv_kernel<<<dim3(16, 32, 3), blk, SMEM_DYN>>>(bq, bk, bv);
    scores_kernel<<<dim3(16, 16, 32), blk, SMEM_DYN>>>(alibi);
    ctx_kernel<<<dim3(1, 16, 32), blk, CTX_SMEM>>>();
    out_kernel<<<dim3(16, 32), blk, SMEM_DYN>>>(bd, residual, out);
}